// round 13
// baseline (speedup 1.0000x reference)
#include <cuda_runtime.h>
#include <stdint.h>

// out[s] = float(in[0] ^ ... ^ in[s]), in: [4096, 8192] int32 0/1, out float32.
// Single-pass decoupled-lookback XOR scan. R13: occupancy push.
//  - VPT=4 (16 data regs), __launch_bounds__(512,3) -> 3 blocks/SM, occ ~70%
//  - LANES=32 (warp-wide tiles), GRPS=16, 64 rows/chunk, NCHUNK=64, NTILE=64
//  - group-0-only lookback, exc broadcast via smem
//  - epoch-encoded flags (replay-safe), same-thread release/acquire ordering

#define SEQ      4096
#define COLS_I32 8192
#define ROW_I4   (COLS_I32 / 4)          // 2048 int4 per row

#define NTILE    64                      // column tiles
#define LANES    32                      // int4 lanes per tile (one warp wide)
#define GRPS     16                      // row groups (warps) per block
#define VPT      4                       // rows per thread
#define ROWS_PER_CHUNK (GRPS * VPT)      // 64
#define NCHUNK   (SEQ / ROWS_PER_CHUNK)  // 64
#define THREADS  (LANES * GRPS)          // 512
#define NBLOCKS  (NTILE * NCHUNK)        // 4096 = 2^12

__device__ int4         g_agg[(size_t)NTILE * NCHUNK * LANES];   // 2 MB
__device__ int4         g_inc[(size_t)NTILE * NCHUNK * LANES];   // 2 MB
__device__ int          g_flags[NTILE * NCHUNK * LANES];         // 512 KB
__device__ unsigned int g_ticket;                                // never reset

__device__ __forceinline__ int4 x4(int4 a, int4 b) {
    a.x ^= b.x; a.y ^= b.y; a.z ^= b.z; a.w ^= b.w; return a;
}
__device__ __forceinline__ int ld_acq(const int* p) {
    int v;
    asm volatile("ld.acquire.gpu.global.b32 %0, [%1];" : "=r"(v) : "l"(p) : "memory");
    return v;
}
__device__ __forceinline__ void st_rel(int* p, int v) {
    asm volatile("st.release.gpu.global.b32 [%0], %1;" :: "l"(p), "r"(v) : "memory");
}
__device__ __forceinline__ float4 tofloat01(int4 r) {
    float4 f;
    f.x = __int_as_float(r.x * 0x3f800000);
    f.y = __int_as_float(r.y * 0x3f800000);
    f.z = __int_as_float(r.z * 0x3f800000);
    f.w = __int_as_float(r.w * 0x3f800000);
    return f;
}

__global__ __launch_bounds__(THREADS, 3)
void xorscan_kernel(const int4* __restrict__ in, float4* __restrict__ out) {
    __shared__ unsigned int sh_ticket;
    __shared__ int4 sh_agg[GRPS][LANES];   // 8 KB
    __shared__ int4 sh_exc[LANES];         // 512 B

    const int tid = threadIdx.x;
    if (tid == 0) sh_ticket = atomicAdd(&g_ticket, 1u);
    __syncthreads();
    const unsigned int ticket = sh_ticket;
    const unsigned int lt     = ticket & (NBLOCKS - 1);
    const int epoch2 = (int)((ticket >> 12) * 2u);       // 2*epoch, NBLOCKS=2^12
    const int tile   = (int)(lt & (NTILE - 1));          // fill all tiles first
    const int chunk  = (int)(lt >> 6);                   // NTILE = 64

    const int lane = tid & (LANES - 1);
    const int grp  = tid >> 5;                           // warp id

    const long row0 = (long)chunk * ROWS_PER_CHUNK + (long)grp * VPT;
    const long base = row0 * ROW_I4 + (long)tile * LANES + lane;

    // ---- load + thread-local inclusive XOR scan ----
    int4 v[VPT];
#pragma unroll
    for (int i = 0; i < VPT; i++) v[i] = __ldcs(&in[base + (long)i * ROW_I4]);
#pragma unroll
    for (int i = 1; i < VPT; i++) v[i] = x4(v[i], v[i - 1]);

    // ---- cross-group combine via smem ----
    sh_agg[grp][lane] = v[VPT - 1];
    __syncthreads();

    int4 gexc = make_int4(0, 0, 0, 0);   // XOR of group aggregates below mine
    int4 bagg = make_int4(0, 0, 0, 0);   // full block aggregate for my lane
#pragma unroll
    for (int g = 0; g < GRPS; g++) {
        int4 a = sh_agg[g][lane];
        if (g < grp) gexc = x4(gexc, a);
        bagg = x4(bagg, a);
    }

    const size_t lidx = (size_t)(tile * NCHUNK + chunk) * LANES + lane;

    // ---- group 0: publish aggregate, lookback, publish inclusive ----
    if (grp == 0) {
        if (chunk > 0) {
            g_agg[lidx] = bagg;
            st_rel(&g_flags[lidx], epoch2 + 1);
        }
        int4 exc = make_int4(0, 0, 0, 0);
        if (chunk > 0) {
            int look = chunk - 1;
            while (true) {
                const size_t pidx = (size_t)(tile * NCHUNK + look) * LANES + lane;
                int s;
                do { s = ld_acq(&g_flags[pidx]); } while (s <= epoch2);
                if (s == epoch2 + 2) {                    // inclusive available
                    exc = x4(exc, __ldcg(&g_inc[pidx]));
                    break;
                }
                exc = x4(exc, __ldcg(&g_agg[pidx]));      // aggregate, walk on
                look--;
            }
        }
        g_inc[lidx] = x4(exc, bagg);
        st_rel(&g_flags[lidx], epoch2 + 2);
        sh_exc[lane] = exc;
    }
    __syncthreads();

    // ---- apply prefix, convert to float, stream out ----
    const int4 pre = x4(sh_exc[lane], gexc);
#pragma unroll
    for (int i = 0; i < VPT; i++) {
        __stcs(&out[base + (long)i * ROW_I4], tofloat01(x4(v[i], pre)));
    }
}

extern "C" void kernel_launch(void* const* d_in, const int* in_sizes, int n_in,
                              void* d_out, int out_size) {
    const int4* in  = (const int4*)d_in[0];
    float4*     out = (float4*)d_out;
    xorscan_kernel<<<NBLOCKS, THREADS>>>(in, out);
}

// round 14
// speedup vs baseline: 2.1193x; 2.1193x over previous
#include <cuda_runtime.h>
#include <stdint.h>

// out[s] = float(in[0] ^ ... ^ in[s]), in: [4096, 8192] int32 0/1, out float32.
// Single-pass decoupled-lookback XOR scan. R14: warp-specialized lookback.
//  - R12 geometry (proven best): NTILE=64 x LANES=32, GRPS=16, VPT=8,
//    128 rows/chunk, NCHUNK=32, NBLOCKS=2048.
//  - Warp 16 (the 17th) runs the lookback from kernel start, overlapping the
//    data warps' load phase. Data warps sync via named barrier 1 (512 thr);
//    one __syncthreads() joins everyone when exc is ready.
//  - epoch-encoded flags (replay-safe), same-thread release/acquire ordering.

#define SEQ      4096
#define COLS_I32 8192
#define ROW_I4   (COLS_I32 / 4)          // 2048 int4 per row

#define NTILE    64                      // column tiles
#define LANES    32                      // int4 lanes per tile (one warp wide)
#define GRPS     16                      // data warps per block
#define VPT      8                       // rows per thread
#define ROWS_PER_CHUNK (GRPS * VPT)      // 128
#define NCHUNK   (SEQ / ROWS_PER_CHUNK)  // 32
#define DATA_THREADS (LANES * GRPS)      // 512
#define THREADS  (DATA_THREADS + 32)     // 544: +1 lookback warp
#define NBLOCKS  (NTILE * NCHUNK)        // 2048 = 2^11

__device__ int4         g_agg[(size_t)NTILE * NCHUNK * LANES];   // 1 MB
__device__ int4         g_inc[(size_t)NTILE * NCHUNK * LANES];   // 1 MB
__device__ int          g_flags[NTILE * NCHUNK * LANES];         // 256 KB
__device__ unsigned int g_ticket;                                // never reset

__device__ __forceinline__ int4 x4(int4 a, int4 b) {
    a.x ^= b.x; a.y ^= b.y; a.z ^= b.z; a.w ^= b.w; return a;
}
__device__ __forceinline__ int ld_acq(const int* p) {
    int v;
    asm volatile("ld.acquire.gpu.global.b32 %0, [%1];" : "=r"(v) : "l"(p) : "memory");
    return v;
}
__device__ __forceinline__ void st_rel(int* p, int v) {
    asm volatile("st.release.gpu.global.b32 [%0], %1;" :: "l"(p), "r"(v) : "memory");
}
__device__ __forceinline__ float4 tofloat01(int4 r) {
    float4 f;
    f.x = __int_as_float(r.x * 0x3f800000);
    f.y = __int_as_float(r.y * 0x3f800000);
    f.z = __int_as_float(r.z * 0x3f800000);
    f.w = __int_as_float(r.w * 0x3f800000);
    return f;
}

__global__ __launch_bounds__(THREADS, 2)
void xorscan_kernel(const int4* __restrict__ in, float4* __restrict__ out) {
    __shared__ unsigned int sh_ticket;
    __shared__ int4 sh_agg[GRPS][LANES];   // 8 KB
    __shared__ int4 sh_exc[LANES];         // 512 B

    const int tid = threadIdx.x;
    if (tid == 0) sh_ticket = atomicAdd(&g_ticket, 1u);
    __syncthreads();
    const unsigned int ticket = sh_ticket;
    const unsigned int lt     = ticket & (NBLOCKS - 1);
    const int epoch2 = (int)((ticket >> 11) * 2u);       // 2*epoch
    const int tile   = (int)(lt & (NTILE - 1));          // fill all tiles first
    const int chunk  = (int)(lt >> 6);                   // NTILE = 64

    const int lane = tid & (LANES - 1);
    const int grp  = tid >> 5;                           // 0..16

    if (grp == GRPS) {
        // ---------- lookback warp: runs concurrently with load phase ----------
        int4 exc = make_int4(0, 0, 0, 0);
        if (chunk > 0) {
            int look = chunk - 1;
            while (true) {
                const size_t pidx = (size_t)(tile * NCHUNK + look) * LANES + lane;
                int s;
                do { s = ld_acq(&g_flags[pidx]); } while (s <= epoch2);
                if (s == epoch2 + 2) {                    // inclusive available
                    exc = x4(exc, __ldcg(&g_inc[pidx]));
                    break;
                }
                exc = x4(exc, __ldcg(&g_agg[pidx]));      // aggregate, walk on
                look--;
            }
        }
        sh_exc[lane] = exc;
        __syncthreads();                                  // join J1
        return;
    }

    // ---------------- data warps ----------------
    const long row0 = (long)chunk * ROWS_PER_CHUNK + (long)grp * VPT;
    const long base = row0 * ROW_I4 + (long)tile * LANES + lane;

    int4 v[VPT];
#pragma unroll
    for (int i = 0; i < VPT; i++) v[i] = __ldcs(&in[base + (long)i * ROW_I4]);
#pragma unroll
    for (int i = 1; i < VPT; i++) v[i] = x4(v[i], v[i - 1]);

    sh_agg[grp][lane] = v[VPT - 1];
    asm volatile("bar.sync 1, %0;" :: "n"(DATA_THREADS) : "memory");  // data-only

    int4 gexc = make_int4(0, 0, 0, 0);
    int4 bagg = make_int4(0, 0, 0, 0);
#pragma unroll
    for (int g = 0; g < GRPS; g++) {
        int4 a = sh_agg[g][lane];
        if (g < grp) gexc = x4(gexc, a);
        bagg = x4(bagg, a);
    }

    const size_t lidx = (size_t)(tile * NCHUNK + chunk) * LANES + lane;

    // publish aggregate as early as possible (successors are spinning on it)
    if (grp == 0 && chunk > 0) {
        g_agg[lidx] = bagg;
        st_rel(&g_flags[lidx], epoch2 + 1);
    }

    __syncthreads();                                      // join J1: exc ready
    const int4 exc = sh_exc[lane];

    // publish inclusive (gates deep lookbacks of successors)
    if (grp == 0) {
        g_inc[lidx] = x4(exc, bagg);
        st_rel(&g_flags[lidx], epoch2 + 2);
    }

    const int4 pre = x4(exc, gexc);
#pragma unroll
    for (int i = 0; i < VPT; i++) {
        __stcs(&out[base + (long)i * ROW_I4], tofloat01(x4(v[i], pre)));
    }
}

extern "C" void kernel_launch(void* const* d_in, const int* in_sizes, int n_in,
                              void* d_out, int out_size) {
    const int4* in  = (const int4*)d_in[0];
    float4*     out = (float4*)d_out;
    xorscan_kernel<<<NBLOCKS, THREADS>>>(in, out);
}